// round 8
// baseline (speedup 1.0000x reference)
#include <cuda_runtime.h>
#include <cuda_bf16.h>
#include <cstdint>

#define A_   50
#define T_   50
#define HID_ 128
#define H_   32
#define C_   16
#define B_   32
#define S_   2450          // T_*(A_-1)
#define HC_  512           // H_*C_
#define NEG_SLOPE 0.2f
#define NB   51            // buckets 0..50

// ---------------- scratch (device globals; no allocations allowed) --------
__device__ float g_vdst[H_ * HID_];                         // [h][d]
__device__ __align__(16) __nv_bfloat16 g_Whi[HC_ * HID_];   // [n][k]
__device__ __align__(16) __nv_bfloat16 g_Wlo[HC_ * HID_];   // [n][k]
__device__ float g_eth[B_ * H_ * 64];                       // sorted thresholds (+INF pad)
__device__ float g_e1[B_ * H_ * T_];
__device__ float g_e2[B_ * H_ * T_];
__device__ int   g_perm[B_ * H_ * T_];
__device__ __align__(16) float g_bkt[(size_t)B_ * H_ * 2 * NB * 16];  // 6.7 MB
__device__ float g_qbk[B_ * H_ * 2 * NB];

__device__ __forceinline__ uint32_t pack_bf16(float a, float b) {
    __nv_bfloat162 t = __floats2bfloat162_rn(a, b);
    return *reinterpret_cast<uint32_t*>(&t);
}

// mma.sync m16n8k16 row.col f32.bf16.bf16.f32
__device__ __forceinline__ void mma_bf16(float* c, const uint32_t* a, const uint32_t* b) {
    asm volatile(
        "mma.sync.aligned.m16n8k16.row.col.f32.bf16.bf16.f32 "
        "{%0,%1,%2,%3}, {%4,%5,%6,%7}, {%8,%9}, {%0,%1,%2,%3};"
        : "+f"(c[0]), "+f"(c[1]), "+f"(c[2]), "+f"(c[3])
        : "r"(a[0]), "r"(a[1]), "r"(a[2]), "r"(a[3]), "r"(b[0]), "r"(b[1]));
}

// ---- fused kernel smem layout (bytes); M=64 rows, 4 heads (N=64) ----
#define ASTR   136
#define OSTR   68
#define NT     39                      // ceil(2450/64)
#define FB_WHI  0                      // 17408
#define FB_WLO  17408                  // 17408
#define FB_AHI  34816                  // 17408
#define FB_ALO  52224                  // 17408
#define FB_OUTS FB_AHI                 // 64*68*4 = 17408, aliases A (consumed first)
#define FB_BKT  69632                  // 4h*2arr*53*16*4 = 27136
#define FB_QBK  96768                  // 4*2*53*4 = 1696
#define FB_ETH  98464                  // 4*64*4 = 1024
#define FB_ASC  99488                  // 4*16*4 = 256
#define FB_QS1  99744                  // 4*64*4
#define FB_QS2  100768
#define FB_RO   101792
#define SMEM_FUSED 102816
#define TRASH  816                     // 51*16: scratch row for dup merge

// ---------------- prep: bf16-split W, contract att_dst into v_dst ----------
__global__ void prep_kernel(const float* __restrict__ W,
                            const float* __restrict__ att_dst) {
    int idx = blockIdx.x * blockDim.x + threadIdx.x;
    if (idx < HID_ * HC_) {
        float w = W[idx];
        __nv_bfloat16 hi = __float2bfloat16(w);
        g_Whi[idx] = hi;
        g_Wlo[idx] = __float2bfloat16(w - __bfloat162float(hi));
    }
    if (idx < H_ * HID_) {
        int h = idx / HID_, d = idx % HID_;
        float s2 = 0.f;
        #pragma unroll
        for (int c = 0; c < C_; c++)
            s2 += W[(h * C_ + c) * HID_ + d] * att_dst[h * C_ + c];
        g_vdst[idx] = s2;
    }
}

// ---------------- a_dst + sort thresholds per (b,h) ------------------------
__global__ __launch_bounds__(64) void adst_sort_kernel(const float* __restrict__ hin) {
    __shared__ float hs[T_ * 129];
    __shared__ float vd[HID_];
    __shared__ float dv[64];
    __shared__ float eth[64];
    __shared__ int per[64];
    int h = blockIdx.x, b = blockIdx.y, tid = threadIdx.x;

    for (int i = tid; i < T_ * HID_; i += 64) {
        int t = i >> 7, d = i & 127;
        hs[t * 129 + d] = hin[(size_t)(b * A_) * T_ * HID_ + i];   // ego rows contiguous
    }
    for (int i = tid; i < HID_; i += 64) vd[i] = g_vdst[h * HID_ + i];
    __syncthreads();

    float dd = 0.f, key = __int_as_float(0x7f800000);
    if (tid < T_) {
        const float* hr = &hs[tid * 129];
        float a = 0.f;
        #pragma unroll 16
        for (int d = 0; d < HID_; d++) a += hr[d] * vd[d];
        dd = a;
        key = __expf(-a);
    }
    dv[tid] = dd; eth[tid] = key; per[tid] = tid;

    for (int k = 2; k <= 64; k <<= 1) {
        for (int j = k >> 1; j > 0; j >>= 1) {
            __syncthreads();
            int ixj = tid ^ j;
            if (ixj > tid) {
                float a = eth[tid], c2 = eth[ixj];
                bool up = ((tid & k) == 0);
                if (up ? (a > c2) : (a < c2)) {
                    eth[tid] = c2; eth[ixj] = a;
                    int p = per[tid]; per[tid] = per[ixj]; per[ixj] = p;
                }
            }
        }
    }
    __syncthreads();

    g_eth[(b * H_ + h) * 64 + tid] = eth[tid];
    if (tid < T_) {
        float d2 = dv[per[tid]];
        int o = (b * H_ + h) * T_ + tid;
        g_e1[o] = __expf(d2);
        g_e2[o] = __expf(NEG_SLOPE * d2);
        g_perm[o] = per[tid];
    }
}

// ---------------- fill entire output with broadcast bias -------------------
__global__ void fill_kernel(float* __restrict__ out, const float* __restrict__ bias, int n4) {
    int idx = blockIdx.x * blockDim.x + threadIdx.x;
    int stride = gridDim.x * blockDim.x;
    float4 v = ((const float4*)bias)[idx & 127];
    for (; idx < n4; idx += stride)
        ((float4*)out)[idx] = v;
}

// ---------------- fused GEMM + bucket accumulation, 2 CTAs/SM --------------
// grid (8 head-blocks, 32 b); CTA owns 4 heads (N=64), M=64 rows, 39 tiles.
__global__ __launch_bounds__(256, 2) void fused_kernel(const float* __restrict__ hin,
                                                       const float* __restrict__ att_src) {
    extern __shared__ char sm[];
    int tid = threadIdx.x, wid = tid >> 5, lane = tid & 31;
    int nb = blockIdx.x, b = blockIdx.y;
    int n0 = nb * 64, h0 = nb * 4;

    // ---- resident W (bf16 hi/lo), att_src, thresholds; zero buckets ----
    #pragma unroll
    for (int i = 0; i < 4; i++) {
        int slot = tid + 256 * i;          // 1024 slots = 64 rows x 16 k8
        int row = slot >> 4, k8 = slot & 15;
        size_t off = (size_t)(row * ASTR + k8 * 8) * 2;
        *(uint4*)(sm + FB_WHI + off) = *(const uint4*)&g_Whi[(n0 + row) * HID_ + k8 * 8];
        *(uint4*)(sm + FB_WLO + off) = *(const uint4*)&g_Wlo[(n0 + row) * HID_ + k8 * 8];
    }
    if (tid < 64) ((float*)(sm + FB_ASC))[tid] = att_src[h0 * 16 + tid];
    ((float*)(sm + FB_ETH))[tid] = g_eth[(b * H_ + h0) * 64 + tid];
    for (int i = tid; i < (27136 + 1696) / 4; i += 256)
        ((float*)(sm + FB_BKT))[i] = 0.f;

    int wm = wid & 3, wn = wid >> 2;       // m block 16 rows, n block 32 cols
    int at = lane >> 2, kq = (lane & 3) * 2;

    for (int tile = 0; tile < NT; tile++) {
        int s0 = tile * 64;
        __syncthreads();   // tables ready (t0); prev step2 done with outs (t>0)

        // ---- load + split-convert A tile (64 rows) ----
        #pragma unroll
        for (int i = 0; i < 8; i++) {
            int slot = tid + 256 * i;       // 2048 float4 slots
            int row = slot >> 5, k4 = slot & 31;
            int s = s0 + row;
            float4 v = make_float4(0.f, 0.f, 0.f, 0.f);
            if (s < S_) {
                int a = s % 49 + 1, t = s / 49;
                v = *(const float4*)&hin[(((b * A_ + a) * T_ + t) * HID_) + k4 * 4];
            }
            float hx = __bfloat162float(__float2bfloat16(v.x));
            float hy = __bfloat162float(__float2bfloat16(v.y));
            float hz = __bfloat162float(__float2bfloat16(v.z));
            float hw = __bfloat162float(__float2bfloat16(v.w));
            uint2 hv = make_uint2(pack_bf16(v.x, v.y), pack_bf16(v.z, v.w));
            uint2 lv = make_uint2(pack_bf16(v.x - hx, v.y - hy), pack_bf16(v.z - hz, v.w - hw));
            size_t off = (size_t)(row * ASTR + k4 * 4) * 2;
            *(uint2*)(sm + FB_AHI + off) = hv;
            *(uint2*)(sm + FB_ALO + off) = lv;
        }
        __syncthreads();

        // ---- MMA mainloop: warp tile 16(m) x 32(n) ----
        float acc[4][4];
        #pragma unroll
        for (int nt = 0; nt < 4; nt++)
            #pragma unroll
            for (int j = 0; j < 4; j++) acc[nt][j] = 0.f;

        const uint16_t* Ah = (const uint16_t*)(sm + FB_AHI);
        const uint16_t* Al = (const uint16_t*)(sm + FB_ALO);
        const uint16_t* Wh = (const uint16_t*)(sm + FB_WHI);
        const uint16_t* Wl = (const uint16_t*)(sm + FB_WLO);

        #pragma unroll
        for (int ks = 0; ks < 8; ks++) {
            int k0 = ks * 16;
            uint32_t ah[4], al[4], bh[4][2], bl[4][2];
            {
                int r = wm * 16 + at;
                int base0 = r * ASTR + k0 + kq;
                int base1 = (r + 8) * ASTR + k0 + kq;
                ah[0] = *(const uint32_t*)&Ah[base0];
                ah[1] = *(const uint32_t*)&Ah[base1];
                ah[2] = *(const uint32_t*)&Ah[base0 + 8];
                ah[3] = *(const uint32_t*)&Ah[base1 + 8];
                al[0] = *(const uint32_t*)&Al[base0];
                al[1] = *(const uint32_t*)&Al[base1];
                al[2] = *(const uint32_t*)&Al[base0 + 8];
                al[3] = *(const uint32_t*)&Al[base1 + 8];
            }
            #pragma unroll
            for (int nt = 0; nt < 4; nt++) {
                int n = wn * 32 + nt * 8 + at;
                int base = n * ASTR + k0 + kq;
                bh[nt][0] = *(const uint32_t*)&Wh[base];
                bh[nt][1] = *(const uint32_t*)&Wh[base + 8];
                bl[nt][0] = *(const uint32_t*)&Wl[base];
                bl[nt][1] = *(const uint32_t*)&Wl[base + 8];
            }
            #pragma unroll
            for (int nt = 0; nt < 4; nt++) {
                mma_bf16(acc[nt], ah, bh[nt]);
                mma_bf16(acc[nt], ah, bl[nt]);
                mma_bf16(acc[nt], al, bh[nt]);
            }
        }
        __syncthreads();    // done reading A; outs may overwrite

        // ---- stage D ----
        float* outs = (float*)(sm + FB_OUTS);
        {
            int r = wm * 16 + at;
            #pragma unroll
            for (int nt = 0; nt < 4; nt++) {
                int cc = wn * 32 + nt * 8 + kq;
                *(float2*)&outs[r * OSTR + cc]       = make_float2(acc[nt][0], acc[nt][1]);
                *(float2*)&outs[(r + 8) * OSTR + cc] = make_float2(acc[nt][2], acc[nt][3]);
            }
        }
        __syncthreads();

        // ---- step1: a_src -> q1,q2,bucket per (srow, head) ----
        float* qs1 = (float*)(sm + FB_QS1);
        float* qs2 = (float*)(sm + FB_QS2);
        int*   rox = (int*)(sm + FB_RO);
        {
            int srow = tid & 63, hl = tid >> 6;    // 256 = 64 rows x 4 heads
            const float* orow = outs + srow * OSTR + hl * 16;
            const float* wv = (const float*)(sm + FB_ASC) + hl * 16;
            float dot = 0.f;
            #pragma unroll
            for (int cq = 0; cq < 4; cq++) {
                float4 v = *(const float4*)&orow[cq * 4];
                float4 w = *(const float4*)&wv[cq * 4];
                dot += v.x * w.x + v.y * w.y + v.z * w.z + v.w * w.w;
            }
            float v1 = 0.f, v2 = 0.f;
            int r = 0;
            if (s0 + srow < S_) {
                v1 = __expf(dot);
                v2 = __expf(NEG_SLOPE * dot);
                const float* e = (const float*)(sm + FB_ETH) + hl * 64;
                if (e[r + 31] < v1) r += 32;
                if (e[r + 15] < v1) r += 16;
                if (e[r + 7]  < v1) r += 8;
                if (e[r + 3]  < v1) r += 4;
                if (e[r + 1]  < v1) r += 2;
                if (e[r]      < v1) r += 1;
            }
            qs1[hl * 64 + srow] = v1;
            qs2[hl * 64 + srow] = v2;
            rox[hl * 64 + srow] = r * 16;
        }
        __syncthreads();

        // ---- step2: warp = (head, arr); lanes 0-15 B, lane 16 Q ----
        {
            int hl = wid >> 1, arr = wid & 1;
            int c = lane & 15;
            bool doB = lane < 16, doQ = (lane == 16);
            float* bk = (float*)(sm + FB_BKT) + (hl * 2 + arr) * 848 + c;
            float* qb = (float*)(sm + FB_QBK) + (hl * 2 + arr) * 53;
            const float* qarr = (arr ? qs2 : qs1) + hl * 64;
            const int* rop = rox + hl * 64;
            const float* ox = outs + hl * 16 + c;
            if (doB | doQ) {
                for (int s4 = 0; s4 < 64; s4 += 4) {
                    int r0 = rop[s4], r1 = rop[s4 + 1], r2 = rop[s4 + 2], r3 = rop[s4 + 3];
                    float q0 = qarr[s4], q1v = qarr[s4 + 1], q2v = qarr[s4 + 2], q3v = qarr[s4 + 3];
                    float x0 = ox[s4 * OSTR], x1 = ox[(s4 + 1) * OSTR];
                    float x2 = ox[(s4 + 2) * OSTR], x3 = ox[(s4 + 3) * OSTR];
                    float v0 = q0 * x0, v1 = q1v * x1, v2 = q2v * x2, v3 = q3v * x3;
                    float w0 = q0, w1 = q1v, w2 = q2v, w3 = q3v;
                    // dup-merge: guarantee r0..r3 distinct (dups -> TRASH)
                    if (r1 == r0) { v0 += v1; w0 += w1; r1 = TRASH; v1 = 0.f; w1 = 0.f; }
                    if (r2 == r0) { v0 += v2; w0 += w2; r2 = TRASH; v2 = 0.f; w2 = 0.f; }
                    else if (r2 == r1) { v1 += v2; w1 += w2; r2 = TRASH; v2 = 0.f; w2 = 0.f; }
                    if (r3 == r0) { v0 += v3; w0 += w3; r3 = TRASH; v3 = 0.f; w3 = 0.f; }
                    else if (r3 == r1) { v1 += v3; w1 += w3; r3 = TRASH; v3 = 0.f; w3 = 0.f; }
                    else if (r3 == r2) { v2 += v3; w2 += w3; r3 = TRASH; v3 = 0.f; w3 = 0.f; }
                    if (doB) {
                        float b0 = bk[r0], b1 = bk[r1], b2 = bk[r2], b3 = bk[r3];
                        bk[r0] = b0 + v0; bk[r1] = b1 + v1; bk[r2] = b2 + v2; bk[r3] = b3 + v3;
                    } else {
                        float c0 = qb[r0 >> 4], c1 = qb[r1 >> 4], c2 = qb[r2 >> 4], c3 = qb[r3 >> 4];
                        qb[r0 >> 4] = c0 + w0; qb[r1 >> 4] = c1 + w1;
                        qb[r2 >> 4] = c2 + w2; qb[r3 >> 4] = c3 + w3;
                    }
                }
            }
        }
    }
    __syncthreads();

    // ---- write bucket sums to global ----
    const float* bks = (const float*)(sm + FB_BKT);
    for (int i = tid; i < 4 * 2 * NB * 16; i += 256) {
        int c = i & 15;
        int hr = i >> 4;                    // hl*102 + arr*51 + r
        int hl = hr / 102, rem = hr % 102;
        int arr = rem / NB, r = rem % NB;
        g_bkt[((size_t)((b * H_ + h0 + hl) * 2 + arr) * NB + r) * 16 + c] =
            bks[(hl * 2 + arr) * 848 + r * 16 + c];
    }
    const float* qbs = (const float*)(sm + FB_QBK);
    for (int i = tid; i < 4 * 2 * NB; i += 256) {
        int hl = i / (2 * NB), rem = i % (2 * NB);
        int arr = rem / NB, r = rem % NB;
        g_qbk[((b * H_ + h0 + hl) * 2 + arr) * NB + r] = qbs[(hl * 2 + arr) * 53 + r];
    }
}

// ---------------- finish: scans + Z + output --------------------------------
__global__ __launch_bounds__(64) void finish_kernel(float* __restrict__ out,
                                                    const float* __restrict__ bias) {
    __shared__ float BS[2 * NB * 16];
    __shared__ float QS[2 * NB];
    __shared__ float e1s[T_], e2s[T_], Zs[T_];
    __shared__ int per[T_];
    int h = blockIdx.x, b = blockIdx.y, tid = threadIdx.x;

    const float* gb = g_bkt + (size_t)(b * H_ + h) * 2 * NB * 16;
    for (int i = tid; i < 2 * NB * 16; i += 64) BS[i] = gb[i];
    const float* gq = g_qbk + (b * H_ + h) * 2 * NB;
    for (int i = tid; i < 2 * NB; i += 64) QS[i] = gq[i];
    if (tid < T_) {
        int o = (b * H_ + h) * T_ + tid;
        e1s[tid] = g_e1[o];
        e2s[tid] = g_e2[o];
        per[tid] = g_perm[o];
    }
    __syncthreads();

    if (tid < 32) {
        int arr = tid >> 4, c = tid & 15;
        float run = 0.f;
        if (arr == 0) {
            for (int r = NB - 1; r >= 0; r--) { run += BS[r * 16 + c]; BS[r * 16 + c] = run; }
        } else {
            for (int r = 0; r < NB; r++) { run += BS[(NB + r) * 16 + c]; BS[(NB + r) * 16 + c] = run; }
        }
    } else if (tid < 34) {
        int arr = tid - 32;
        float run = 0.f;
        if (arr == 0) {
            for (int r = NB - 1; r >= 0; r--) { run += QS[r]; QS[r] = run; }
        } else {
            for (int r = 0; r < NB; r++) { run += QS[NB + r]; QS[NB + r] = run; }
        }
    }
    __syncthreads();

    if (tid < T_)
        Zs[tid] = 1.0f / (e1s[tid] * QS[tid + 1] + e2s[tid] * QS[NB + tid]);
    __syncthreads();

    for (int i = tid; i < T_ * 16; i += 64) {
        int si = i >> 4, c = i & 15;
        int t = per[si];
        float o = Zs[si] * (e1s[si] * BS[(si + 1) * 16 + c] + e2s[si] * BS[(NB + si) * 16 + c]);
        out[((size_t)(b * A_) * T_ + t) * HC_ + h * C_ + c] = o + bias[h * C_ + c];
    }
}

// ---------------------------------------------------------------------------
extern "C" void kernel_launch(void* const* d_in, const int* in_sizes, int n_in,
                              void* d_out, int out_size) {
    const float* hin     = (const float*)d_in[0];
    const float* W       = (const float*)d_in[1];
    const float* att_src = (const float*)d_in[2];
    const float* att_dst = (const float*)d_in[3];
    const float* bias    = (const float*)d_in[4];
    float* out = (float*)d_out;

    cudaFuncSetAttribute(fused_kernel, cudaFuncAttributeMaxDynamicSharedMemorySize, SMEM_FUSED);

    prep_kernel<<<(HID_ * HC_ + 255) / 256, 256>>>(W, att_dst);

    dim3 gs(H_, B_);
    adst_sort_kernel<<<gs, 64>>>(hin);

    fill_kernel<<<2048, 256>>>(out, bias, out_size / 4);

    dim3 gf(8, B_);
    fused_kernel<<<gf, 256, SMEM_FUSED>>>(hin, att_src);

    finish_kernel<<<gs, 64>>>(out, bias);
}

// round 9
// speedup vs baseline: 1.0039x; 1.0039x over previous
#include <cuda_runtime.h>
#include <cuda_bf16.h>
#include <cstdint>

#define A_   50
#define T_   50
#define HID_ 128
#define H_   32
#define C_   16
#define B_   32
#define S_   2450          // T_*(A_-1)
#define HC_  512           // H_*C_
#define NEG_SLOPE 0.2f
#define NB   51            // buckets 0..50

// ---------------- scratch (device globals; no allocations allowed) --------
__device__ float g_vdst[H_ * HID_];                         // [h][d]
__device__ __align__(16) __nv_bfloat16 g_Whi[HC_ * HID_];   // [n][k]
__device__ __align__(16) __nv_bfloat16 g_Wlo[HC_ * HID_];   // [n][k]
__device__ float g_eth[B_ * H_ * 64];                       // sorted thresholds (+INF pad)
__device__ float g_e1[B_ * H_ * T_];
__device__ float g_e2[B_ * H_ * T_];
__device__ int   g_perm[B_ * H_ * T_];
__device__ __align__(16) float g_bkt[(size_t)B_ * H_ * 2 * NB * 16];  // 6.7 MB
__device__ float g_qbk[B_ * H_ * 2 * NB];

__device__ __forceinline__ uint32_t smem_u32(const void* p) {
    uint32_t a;
    asm("{ .reg .u64 t; cvta.to.shared.u64 t, %1; cvt.u32.u64 %0, t; }" : "=r"(a) : "l"(p));
    return a;
}

// mma.sync m16n8k16 row.col f32.bf16.bf16.f32
__device__ __forceinline__ void mma_bf16(float* c, const uint32_t* a, const uint32_t* b) {
    asm volatile(
        "mma.sync.aligned.m16n8k16.row.col.f32.bf16.bf16.f32 "
        "{%0,%1,%2,%3}, {%4,%5,%6,%7}, {%8,%9}, {%0,%1,%2,%3};"
        : "+f"(c[0]), "+f"(c[1]), "+f"(c[2]), "+f"(c[3])
        : "r"(a[0]), "r"(a[1]), "r"(a[2]), "r"(a[3]), "r"(b[0]), "r"(b[1]));
}

#define LDMX4(r0, r1, r2, r3, addr) \
    asm volatile("ldmatrix.sync.aligned.m8n8.x4.shared.b16 {%0,%1,%2,%3}, [%4];" \
        : "=r"(r0), "=r"(r1), "=r"(r2), "=r"(r3) : "r"(addr))

// ---- fused kernel smem layout (bytes); M=64 rows, 4 heads (N=64) ----
#define ASTR   136
#define OSTR   68
#define NT     39                      // ceil(2450/64)
#define FB_WHI  0                      // 17408
#define FB_WLO  17408                  // 17408
#define FB_AHI  34816                  // 17408
#define FB_ALO  52224                  // 17408
#define FB_OUTS FB_AHI                 // 64*68*4 = 17408, aliases A (consumed first)
#define FB_BKT  69632                  // 4h*2arr*53*16*4 = 27136
#define FB_QBK  96768                  // 4*2*53*4 = 1696
#define FB_ETH  98464                  // 4*64*4 = 1024
#define FB_ASC  99488                  // 4*16*4 = 256
#define FB_QS1  99744                  // 4*64*4
#define FB_QS2  100768
#define FB_RO   101792
#define SMEM_FUSED 102816
#define TRASH  816                     // 51*16: scratch row for dup merge

// ---------------- prep: bf16-split W, contract att_dst into v_dst ----------
__global__ void prep_kernel(const float* __restrict__ W,
                            const float* __restrict__ att_dst) {
    int idx = blockIdx.x * blockDim.x + threadIdx.x;
    if (idx < HID_ * HC_) {
        float w = W[idx];
        __nv_bfloat16 hi = __float2bfloat16(w);
        g_Whi[idx] = hi;
        g_Wlo[idx] = __float2bfloat16(w - __bfloat162float(hi));
    }
    if (idx < H_ * HID_) {
        int h = idx / HID_, d = idx % HID_;
        float s2 = 0.f;
        #pragma unroll
        for (int c = 0; c < C_; c++)
            s2 += W[(h * C_ + c) * HID_ + d] * att_dst[h * C_ + c];
        g_vdst[idx] = s2;
    }
}

// ---------------- a_dst + sort thresholds per (b,h) ------------------------
__global__ __launch_bounds__(64) void adst_sort_kernel(const float* __restrict__ hin) {
    __shared__ float hs[T_ * 129];
    __shared__ float vd[HID_];
    __shared__ float dv[64];
    __shared__ float eth[64];
    __shared__ int per[64];
    int h = blockIdx.x, b = blockIdx.y, tid = threadIdx.x;

    for (int i = tid; i < T_ * HID_; i += 64) {
        int t = i >> 7, d = i & 127;
        hs[t * 129 + d] = hin[(size_t)(b * A_) * T_ * HID_ + i];   // ego rows contiguous
    }
    for (int i = tid; i < HID_; i += 64) vd[i] = g_vdst[h * HID_ + i];
    __syncthreads();

    float dd = 0.f, key = __int_as_float(0x7f800000);
    if (tid < T_) {
        const float* hr = &hs[tid * 129];
        float a = 0.f;
        #pragma unroll 16
        for (int d = 0; d < HID_; d++) a += hr[d] * vd[d];
        dd = a;
        key = __expf(-a);
    }
    dv[tid] = dd; eth[tid] = key; per[tid] = tid;

    for (int k = 2; k <= 64; k <<= 1) {
        for (int j = k >> 1; j > 0; j >>= 1) {
            __syncthreads();
            int ixj = tid ^ j;
            if (ixj > tid) {
                float a = eth[tid], c2 = eth[ixj];
                bool up = ((tid & k) == 0);
                if (up ? (a > c2) : (a < c2)) {
                    eth[tid] = c2; eth[ixj] = a;
                    int p = per[tid]; per[tid] = per[ixj]; per[ixj] = p;
                }
            }
        }
    }
    __syncthreads();

    g_eth[(b * H_ + h) * 64 + tid] = eth[tid];
    if (tid < T_) {
        float d2 = dv[per[tid]];
        int o = (b * H_ + h) * T_ + tid;
        g_e1[o] = __expf(d2);
        g_e2[o] = __expf(NEG_SLOPE * d2);
        g_perm[o] = per[tid];
    }
}

// ---------------- fill entire output with broadcast bias -------------------
__global__ void fill_kernel(float* __restrict__ out, const float* __restrict__ bias, int n4) {
    int idx = blockIdx.x * blockDim.x + threadIdx.x;
    int stride = gridDim.x * blockDim.x;
    float4 v = ((const float4*)bias)[idx & 127];
    for (; idx < n4; idx += stride)
        ((float4*)out)[idx] = v;
}

// ---------------- fused GEMM + bucket accumulation, 2 CTAs/SM --------------
// grid (8 head-blocks, 32 b); CTA owns 4 heads (N=64), M=64 rows, 39 tiles.
__global__ __launch_bounds__(256, 2) void fused_kernel(const float* __restrict__ hin,
                                                       const float* __restrict__ att_src) {
    extern __shared__ char sm[];
    uint32_t sbase = smem_u32(sm);
    int tid = threadIdx.x, wid = tid >> 5, lane = tid & 31;
    int nb = blockIdx.x, b = blockIdx.y;
    int n0 = nb * 64, h0 = nb * 4;

    // ---- resident W (bf16 hi/lo), att_src, thresholds; zero buckets ----
    #pragma unroll
    for (int i = 0; i < 4; i++) {
        int slot = tid + 256 * i;          // 1024 slots = 64 rows x 16 k8
        int row = slot >> 4, k8 = slot & 15;
        size_t off = (size_t)(row * ASTR + k8 * 8) * 2;
        *(uint4*)(sm + FB_WHI + off) = *(const uint4*)&g_Whi[(n0 + row) * HID_ + k8 * 8];
        *(uint4*)(sm + FB_WLO + off) = *(const uint4*)&g_Wlo[(n0 + row) * HID_ + k8 * 8];
    }
    if (tid < 64) ((float*)(sm + FB_ASC))[tid] = att_src[h0 * 16 + tid];
    ((float*)(sm + FB_ETH))[tid] = g_eth[(b * H_ + h0) * 64 + tid];
    for (int i = tid; i < (27136 + 1696) / 4; i += 256)
        ((float*)(sm + FB_BKT))[i] = 0.f;

    int wm = wid & 3, wn = wid >> 2;       // m block 16 rows, n block 32 cols
    int at = lane >> 2, kq = (lane & 3) * 2;

    // ---- ldmatrix lane addresses (constant across tiles; +32B per ks) ----
    int g8 = lane >> 3, l8 = lane & 7;
    uint32_t aAddrHi = sbase + FB_AHI +
        ((uint32_t)((wm * 16 + (g8 & 1) * 8 + l8) * ASTR + (g8 >> 1) * 8)) * 2;
    uint32_t aAddrLo = aAddrHi + (FB_ALO - FB_AHI);
    uint32_t bAddrHi0 = sbase + FB_WHI +
        ((uint32_t)((wn * 32 + (g8 >> 1) * 8 + l8) * ASTR + (g8 & 1) * 8)) * 2;
    uint32_t bAddrHi1 = bAddrHi0 + 16 * ASTR * 2;
    uint32_t bAddrLo0 = bAddrHi0 + (FB_WLO - FB_WHI);
    uint32_t bAddrLo1 = bAddrHi1 + (FB_WLO - FB_WHI);

    for (int tile = 0; tile < NT; tile++) {
        int s0 = tile * 64;
        __syncthreads();   // tables ready (t0); prev step2 done with outs (t>0)

        // ---- load + split-convert A tile (64 rows), trunc-split ----
        #pragma unroll
        for (int i = 0; i < 8; i++) {
            int slot = tid + 256 * i;       // 2048 float4 slots
            int row = slot >> 5, k4 = slot & 31;
            int s = s0 + row;
            float4 v = make_float4(0.f, 0.f, 0.f, 0.f);
            if (s < S_) {
                int a = s % 49 + 1, t = s / 49;
                v = *(const float4*)&hin[(((b * A_ + a) * T_ + t) * HID_) + k4 * 4];
            }
            uint32_t ux = __float_as_uint(v.x), uy = __float_as_uint(v.y);
            uint32_t uz = __float_as_uint(v.z), uw = __float_as_uint(v.w);
            // hi = truncate to bf16 (top 16 bits); pack via PRMT
            uint2 hv = make_uint2(__byte_perm(ux, uy, 0x7632),
                                  __byte_perm(uz, uw, 0x7632));
            float lx = v.x - __uint_as_float(ux & 0xffff0000u);
            float ly = v.y - __uint_as_float(uy & 0xffff0000u);
            float lz = v.z - __uint_as_float(uz & 0xffff0000u);
            float lw = v.w - __uint_as_float(uw & 0xffff0000u);
            __nv_bfloat162 l01 = __floats2bfloat162_rn(lx, ly);
            __nv_bfloat162 l23 = __floats2bfloat162_rn(lz, lw);
            uint2 lv = make_uint2(*(uint32_t*)&l01, *(uint32_t*)&l23);
            size_t off = (size_t)(row * ASTR + k4 * 4) * 2;
            *(uint2*)(sm + FB_AHI + off) = hv;
            *(uint2*)(sm + FB_ALO + off) = lv;
        }
        __syncthreads();

        // ---- MMA mainloop: warp tile 16(m) x 32(n), ldmatrix frags ----
        float accA[4][4], accB[4][4];      // hi*hi ; hi*lo + lo*hi
        #pragma unroll
        for (int nt = 0; nt < 4; nt++)
            #pragma unroll
            for (int j = 0; j < 4; j++) { accA[nt][j] = 0.f; accB[nt][j] = 0.f; }

        #pragma unroll
        for (int ks = 0; ks < 8; ks++) {
            uint32_t ko = ks * 32;         // 16 bf16 = 32 bytes per k-step
            uint32_t ah[4], al[4], bh[4][2], bl[4][2];
            LDMX4(ah[0], ah[1], ah[2], ah[3], aAddrHi + ko);
            LDMX4(al[0], al[1], al[2], al[3], aAddrLo + ko);
            LDMX4(bh[0][0], bh[0][1], bh[1][0], bh[1][1], bAddrHi0 + ko);
            LDMX4(bh[2][0], bh[2][1], bh[3][0], bh[3][1], bAddrHi1 + ko);
            LDMX4(bl[0][0], bl[0][1], bl[1][0], bl[1][1], bAddrLo0 + ko);
            LDMX4(bl[2][0], bl[2][1], bl[3][0], bl[3][1], bAddrLo1 + ko);
            #pragma unroll
            for (int nt = 0; nt < 4; nt++) {
                mma_bf16(accA[nt], ah, bh[nt]);
                mma_bf16(accB[nt], ah, bl[nt]);
                mma_bf16(accB[nt], al, bh[nt]);
            }
        }
        __syncthreads();    // done reading A; outs may overwrite

        // ---- stage D (sum split accumulators) ----
        float* outs = (float*)(sm + FB_OUTS);
        {
            int r = wm * 16 + at;
            #pragma unroll
            for (int nt = 0; nt < 4; nt++) {
                int cc = wn * 32 + nt * 8 + kq;
                *(float2*)&outs[r * OSTR + cc] =
                    make_float2(accA[nt][0] + accB[nt][0], accA[nt][1] + accB[nt][1]);
                *(float2*)&outs[(r + 8) * OSTR + cc] =
                    make_float2(accA[nt][2] + accB[nt][2], accA[nt][3] + accB[nt][3]);
            }
        }
        __syncwarp();       // warp-internal: stage visible to own step1

        // ---- step1 (warp-matched): each warp scans its own D quadrant ----
        float* qs1 = (float*)(sm + FB_QS1);
        float* qs2 = (float*)(sm + FB_QS2);
        int*   rox = (int*)(sm + FB_RO);
        {
            int hl = 2 * wn + (lane >> 4);
            int srow = wm * 16 + (lane & 15);
            const float* orow = outs + srow * OSTR + hl * 16;
            const float* wv = (const float*)(sm + FB_ASC) + hl * 16;
            float dot = 0.f;
            #pragma unroll
            for (int cq = 0; cq < 4; cq++) {
                float4 v = *(const float4*)&orow[cq * 4];
                float4 w = *(const float4*)&wv[cq * 4];
                dot += v.x * w.x + v.y * w.y + v.z * w.z + v.w * w.w;
            }
            float v1 = 0.f, v2 = 0.f;
            int r = 0;
            if (s0 + srow < S_) {
                v1 = __expf(dot);
                v2 = __expf(NEG_SLOPE * dot);
                const float* e = (const float*)(sm + FB_ETH) + hl * 64;
                if (e[r + 31] < v1) r += 32;
                if (e[r + 15] < v1) r += 16;
                if (e[r + 7]  < v1) r += 8;
                if (e[r + 3]  < v1) r += 4;
                if (e[r + 1]  < v1) r += 2;
                if (e[r]      < v1) r += 1;
            }
            qs1[hl * 64 + srow] = v1;
            qs2[hl * 64 + srow] = v2;
            rox[hl * 64 + srow] = r * 16;
        }
        __syncthreads();

        // ---- step2: warp = (head, arr); lanes 0-15 B, lane 16 Q ----
        {
            int hl = wid >> 1, arr = wid & 1;
            int c = lane & 15;
            bool doB = lane < 16, doQ = (lane == 16);
            float* bk = (float*)(sm + FB_BKT) + (hl * 2 + arr) * 848 + c;
            float* qb = (float*)(sm + FB_QBK) + (hl * 2 + arr) * 53;
            const float* qarr = (arr ? qs2 : qs1) + hl * 64;
            const int* rop = rox + hl * 64;
            const float* ox = outs + hl * 16 + c;
            if (doB | doQ) {
                for (int s4 = 0; s4 < 64; s4 += 4) {
                    int r0 = rop[s4], r1 = rop[s4 + 1], r2 = rop[s4 + 2], r3 = rop[s4 + 3];
                    float q0 = qarr[s4], q1v = qarr[s4 + 1], q2v = qarr[s4 + 2], q3v = qarr[s4 + 3];
                    float x0 = ox[s4 * OSTR], x1 = ox[(s4 + 1) * OSTR];
                    float x2 = ox[(s4 + 2) * OSTR], x3 = ox[(s4 + 3) * OSTR];
                    float v0 = q0 * x0, v1 = q1v * x1, v2 = q2v * x2, v3 = q3v * x3;
                    float w0 = q0, w1 = q1v, w2 = q2v, w3 = q3v;
                    // dup-merge: guarantee r0..r3 distinct (dups -> TRASH)
                    if (r1 == r0) { v0 += v1; w0 += w1; r1 = TRASH; v1 = 0.f; w1 = 0.f; }
                    if (r2 == r0) { v0 += v2; w0 += w2; r2 = TRASH; v2 = 0.f; w2 = 0.f; }
                    else if (r2 == r1) { v1 += v2; w1 += w2; r2 = TRASH; v2 = 0.f; w2 = 0.f; }
                    if (r3 == r0) { v0 += v3; w0 += w3; r3 = TRASH; v3 = 0.f; w3 = 0.f; }
                    else if (r3 == r1) { v1 += v3; w1 += w3; r3 = TRASH; v3 = 0.f; w3 = 0.f; }
                    else if (r3 == r2) { v2 += v3; w2 += w3; r3 = TRASH; v3 = 0.f; w3 = 0.f; }
                    if (doB) {
                        float b0 = bk[r0], b1 = bk[r1], b2 = bk[r2], b3 = bk[r3];
                        bk[r0] = b0 + v0; bk[r1] = b1 + v1; bk[r2] = b2 + v2; bk[r3] = b3 + v3;
                    } else {
                        float c0 = qb[r0 >> 4], c1 = qb[r1 >> 4], c2 = qb[r2 >> 4], c3 = qb[r3 >> 4];
                        qb[r0 >> 4] = c0 + w0; qb[r1 >> 4] = c1 + w1;
                        qb[r2 >> 4] = c2 + w2; qb[r3 >> 4] = c3 + w3;
                    }
                }
            }
        }
    }
    __syncthreads();

    // ---- write bucket sums to global ----
    const float* bks = (const float*)(sm + FB_BKT);
    for (int i = tid; i < 4 * 2 * NB * 16; i += 256) {
        int c = i & 15;
        int hr = i >> 4;                    // hl*102 + arr*51 + r
        int hl = hr / 102, rem = hr % 102;
        int arr = rem / NB, r = rem % NB;
        g_bkt[((size_t)((b * H_ + h0 + hl) * 2 + arr) * NB + r) * 16 + c] =
            bks[(hl * 2 + arr) * 848 + r * 16 + c];
    }
    const float* qbs = (const float*)(sm + FB_QBK);
    for (int i = tid; i < 4 * 2 * NB; i += 256) {
        int hl = i / (2 * NB), rem = i % (2 * NB);
        int arr = rem / NB, r = rem % NB;
        g_qbk[((b * H_ + h0 + hl) * 2 + arr) * NB + r] = qbs[(hl * 2 + arr) * 53 + r];
    }
}

// ---------------- finish: scans + Z + output --------------------------------
__global__ __launch_bounds__(64) void finish_kernel(float* __restrict__ out,
                                                    const float* __restrict__ bias) {
    __shared__ float BS[2 * NB * 16];
    __shared__ float QS[2 * NB];
    __shared__ float e1s[T_], e2s[T_], Zs[T_];
    __shared__ int per[T_];
    int h = blockIdx.x, b = blockIdx.y, tid = threadIdx.x;

    const float* gb = g_bkt + (size_t)(b * H_ + h) * 2 * NB * 16;
    for (int i = tid; i < 2 * NB * 16; i += 64) BS[i] = gb[i];
    const float* gq = g_qbk + (b * H_ + h) * 2 * NB;
    for (int i = tid; i < 2 * NB; i += 64) QS[i] = gq[i];
    if (tid < T_) {
        int o = (b * H_ + h) * T_ + tid;
        e1s[tid] = g_e1[o];
        e2s[tid] = g_e2[o];
        per[tid] = g_perm[o];
    }
    __syncthreads();

    if (tid < 32) {
        int arr = tid >> 4, c = tid & 15;
        float run = 0.f;
        if (arr == 0) {
            for (int r = NB - 1; r >= 0; r--) { run += BS[r * 16 + c]; BS[r * 16 + c] = run; }
        } else {
            for (int r = 0; r < NB; r++) { run += BS[(NB + r) * 16 + c]; BS[(NB + r) * 16 + c] = run; }
        }
    } else if (tid < 34) {
        int arr = tid - 32;
        float run = 0.f;
        if (arr == 0) {
            for (int r = NB - 1; r >= 0; r--) { run += QS[r]; QS[r] = run; }
        } else {
            for (int r = 0; r < NB; r++) { run += QS[NB + r]; QS[NB + r] = run; }
        }
    }
    __syncthreads();

    if (tid < T_)
        Zs[tid] = 1.0f / (e1s[tid] * QS[tid + 1] + e2s[tid] * QS[NB + tid]);
    __syncthreads();

    for (int i = tid; i < T_ * 16; i += 64) {
        int si = i >> 4, c = i & 15;
        int t = per[si];
        float o = Zs[si] * (e1s[si] * BS[(si + 1) * 16 + c] + e2s[si] * BS[(NB + si) * 16 + c]);
        out[((size_t)(b * A_) * T_ + t) * HC_ + h * C_ + c] = o + bias[h * C_ + c];
    }
}

// ---------------------------------------------------------------------------
extern "C" void kernel_launch(void* const* d_in, const int* in_sizes, int n_in,
                              void* d_out, int out_size) {
    const float* hin     = (const float*)d_in[0];
    const float* W       = (const float*)d_in[1];
    const float* att_src = (const float*)d_in[2];
    const float* att_dst = (const float*)d_in[3];
    const float* bias    = (const float*)d_in[4];
    float* out = (float*)d_out;

    cudaFuncSetAttribute(fused_kernel, cudaFuncAttributeMaxDynamicSharedMemorySize, SMEM_FUSED);

    prep_kernel<<<(HID_ * HC_ + 255) / 256, 256>>>(W, att_dst);

    dim3 gs(H_, B_);
    adst_sort_kernel<<<gs, 64>>>(hin);

    fill_kernel<<<2048, 256>>>(out, bias, out_size / 4);

    dim3 gf(8, B_);
    fused_kernel<<<gf, 256, SMEM_FUSED>>>(hin, att_src);

    finish_kernel<<<gs, 64>>>(out, bias);
}